// round 3
// baseline (speedup 1.0000x reference)
#include <cuda_runtime.h>
#include <cstdint>

// Problem constants (fixed by the reference setup)
#define NB 65536        // batch rows
#define NF 512          // in_features
#define NK 1299         // number of centers
#define WARPS_PER_BLOCK 8
#define NBLOCKS (NB / WARPS_PER_BLOCK)   // 8192 blocks, 1 warp per row

// Scratch for deterministic loss reduction (no device allocs allowed)
__device__ float g_partials[NBLOCKS];

// Kernel 1: per-row gathered dot product + tanh + smooth-L1 term.
// One warp handles one row: 512 floats = 128 float4 = 4 float4 per lane.
__global__ __launch_bounds__(WARPS_PER_BLOCK * 32)
void predict_kernel(const float* __restrict__ input,
                    const float* __restrict__ factor,
                    const int* __restrict__ label,     // JAX downcasts int64->int32
                    const float* __restrict__ centers,
                    float* __restrict__ pred_out)      // points at d_out+1
{
    const int warp = threadIdx.x >> 5;
    const int lane = threadIdx.x & 31;
    const int b = blockIdx.x * WARPS_PER_BLOCK + warp;

    const float4* in4 = reinterpret_cast<const float4*>(input + (size_t)b * NF);
    int c = label[b];
    // cheap insurance: keep gather in-bounds (labels are generated in [0, NK))
    c = (c < 0) ? 0 : (c >= NK ? NK - 1 : c);
    const float4* ce4 = reinterpret_cast<const float4*>(centers + (size_t)c * NF);

    // 4 independent float4 loads per lane from input (coalesced, front-batched)
    // + 4 from centers (L2-resident after warm-up: whole table = 2.6 MB).
    float acc = 0.0f;
#pragma unroll
    for (int i = 0; i < 4; i++) {
        float4 a = in4[lane + 32 * i];
        float4 w = ce4[lane + 32 * i];
        acc += a.x * w.x + a.y * w.y + a.z * w.z + a.w * w.w;
    }

    // Warp reduction
#pragma unroll
    for (int o = 16; o; o >>= 1)
        acc += __shfl_xor_sync(0xffffffffu, acc, o);

    __shared__ float s_loss[WARPS_PER_BLOCK];
    if (lane == 0) {
        float p = 12.0f * tanhf(acc);
        pred_out[b] = p;
        float d = p - factor[b];
        float ad = fabsf(d);
        s_loss[warp] = (ad < 1.0f) ? 0.5f * d * d : (ad - 0.5f);
    }
    __syncthreads();

    if (threadIdx.x == 0) {
        float t = 0.0f;
#pragma unroll
        for (int i = 0; i < WARPS_PER_BLOCK; i++) t += s_loss[i];
        g_partials[blockIdx.x] = t;
    }
}

// Kernel 2: deterministic single-block reduction of the 8192 partials.
__global__ __launch_bounds__(256)
void loss_reduce_kernel(float* __restrict__ out)
{
    __shared__ float s[256];
    float t = 0.0f;
    for (int i = threadIdx.x; i < NBLOCKS; i += 256)
        t += g_partials[i];
    s[threadIdx.x] = t;
    __syncthreads();
#pragma unroll
    for (int o = 128; o; o >>= 1) {
        if (threadIdx.x < o) s[threadIdx.x] += s[threadIdx.x + o];
        __syncthreads();
    }
    if (threadIdx.x == 0)
        out[0] = s[0] * (1.0f / (float)NB);
}

extern "C" void kernel_launch(void* const* d_in, const int* in_sizes, int n_in,
                              void* d_out, int out_size)
{
    // metadata order follows setup_inputs: input, factor, label, centers
    const float* input   = (const float*)d_in[0];
    const float* factor  = (const float*)d_in[1];
    const int*   label   = (const int*)d_in[2];
    const float* centers = (const float*)d_in[3];

    float* out = (float*)d_out;
    // Tuple output flattened: out[0] = loss (scalar), out[1..NB] = predict_a
    float* pred_out = out + 1;

    predict_kernel<<<NBLOCKS, WARPS_PER_BLOCK * 32>>>(input, factor, label, centers, pred_out);
    loss_reduce_kernel<<<1, 256>>>(out);
}